// round 13
// baseline (speedup 1.0000x reference)
#include <cuda_runtime.h>
#include <cuda_fp16.h>
#include <cstdint>

#define D        64
#define HH       64
#define D_INPUT  2145
#define TPB      128

// Pre-swizzled (SW128) fp16 image of M = 1/2(Wu+Wu^T) (diag unhalved).
// Row = n (output dim), col = k (reduction dim). 64 x 128B per h.
__device__ __align__(16) uint8_t g_M[HH][D * 128];
__device__ float g_wl[HH][D];

#define SWZ(off) ((off) ^ (((off) >> 3) & 0x70))

__device__ __forceinline__ uint32_t smem_u32(const void* p) {
    uint32_t a;
    asm("{ .reg .u64 t; cvta.to.shared.u64 t, %1; cvt.u32.u64 %0, t; }" : "=r"(a) : "l"(p));
    return a;
}
__device__ __forceinline__ void ldm_x4(uint32_t* r, uint32_t addr) {
    asm volatile("ldmatrix.sync.aligned.m8n8.x4.shared.b16 {%0,%1,%2,%3}, [%4];"
        : "=r"(r[0]), "=r"(r[1]), "=r"(r[2]), "=r"(r[3]) : "r"(addr));
}
__device__ __forceinline__ void mma_f16(float* c, const uint32_t* a, const uint32_t* b) {
    asm volatile("mma.sync.aligned.m16n8k16.row.col.f32.f16.f16.f32 "
        "{%0,%1,%2,%3}, {%4,%5,%6,%7}, {%8,%9}, {%0,%1,%2,%3};"
        : "+f"(c[0]), "+f"(c[1]), "+f"(c[2]), "+f"(c[3])
        : "r"(a[0]), "r"(a[1]), "r"(a[2]), "r"(a[3]), "r"(b[0]), "r"(b[1]));
}
__device__ __forceinline__ uint32_t h2_of(float2 v) {
    const __half2 h = __floats2half2_rn(v.x, v.y);
    return *reinterpret_cast<const uint32_t*>(&h);
}

// ---------------------------------------------------------------------------
// Prep: stage w row into smem; 512 threads emit one 16B fp16 chunk of the
// symmetric M image. w[h][64+base(i)+(j-i)], base(i)=i*64-i(i-1)/2.
// ---------------------------------------------------------------------------
__global__ void prep_kernel(const float* __restrict__ w) {
    __shared__ float sw[D_INPUT];
    const int h = blockIdx.x;
    for (int i = threadIdx.x; i < D_INPUT; i += 512)
        sw[i] = w[(size_t)h * D_INPUT + i];
    __syncthreads();

    const int t  = threadIdx.x;
    const int n  = t >> 3;
    const int kq = t & 7;

    union { __half b[8]; float4 f; } hb;
    #pragma unroll
    for (int e = 0; e < 8; e++) {
        const int k = kq * 8 + e;
        const int i = k < n ? k : n;
        const int j = k < n ? n : k;
        const float v = sw[D + i * D - (i * (i - 1)) / 2 + (j - i)];
        hb.b[e] = __float2half_rn((k == n) ? v : 0.5f * v);
    }
    const uint32_t sw16 = SWZ((uint32_t)(n * 128 + kq * 16));
    *reinterpret_cast<float4*>(&g_M[h][sw16]) = hb.f;
    if (t < D) g_wl[h][t] = sw[t];
}

// ---------------------------------------------------------------------------
// Main: block = (64-path tile, h), 128 threads / 4 warps. Warp wid owns rows
// wid*16..+16, all 64 cols. A fragments loaded DIRECTLY from gmem (no smem
// round-trip): thread (gid,tig) needs float2 at rows {g, g+8},
// k in {16kt+2tig, +8}. fp32 originals retained for the epilogue.
//   T = O*M,  val = b + sum_n o_n*(wl_n + T_n)
// ---------------------------------------------------------------------------
#define SM_M    0                       // 64 x 128B fp16 M image (SW128)
#define SM_WL   8192                    // 64 fp32
#define SM_TOT  (SM_WL + 256)           // 8448 B

extern __shared__ char smem[];

__global__ __launch_bounds__(TPB, 5)
void vf_kernel(const float* __restrict__ obs,
               const float* __restrict__ biases,
               float* __restrict__ out) {
    const int h     = blockIdx.y;
    const int pbase = blockIdx.x * 64;
    const int tid   = threadIdx.x;
    const int wid   = tid >> 5;
    const int lid   = tid & 31;
    const int gid   = lid >> 2;
    const int tig   = lid & 3;
    const uint32_t sbase = smem_u32(smem);

    const float bval = biases[h];

    // --- Direct A-fragment loads: rows row0 = wid*16+gid, row1 = row0+8;
    //     per kt: k0 = 16kt + 2tig (lo) and k0+8 (hi). 16 LDG.64, front-batched.
    const float* base0 = obs + (size_t)(pbase + wid * 16 + gid) * (HH * D) + (size_t)h * D;
    const float* base1 = base0 + 8 * (HH * D);
    float2 o0lo[4], o1lo[4], o0hi[4], o1hi[4];
    #pragma unroll
    for (int kt = 0; kt < 4; kt++) {
        const int k0 = kt * 16 + 2 * tig;
        o0lo[kt] = *reinterpret_cast<const float2*>(base0 + k0);
        o1lo[kt] = *reinterpret_cast<const float2*>(base1 + k0);
        o0hi[kt] = *reinterpret_cast<const float2*>(base0 + k0 + 8);
        o1hi[kt] = *reinterpret_cast<const float2*>(base1 + k0 + 8);
    }

    // --- Stage M image (pre-swizzled fp16): 512 float4, 4/thread; + wl
    {
        const float4* m4 = reinterpret_cast<const float4*>(&g_M[h][0]);
        float4* sm4 = reinterpret_cast<float4*>(smem + SM_M);
        #pragma unroll
        for (int k = 0; k < 4; k++) sm4[tid + TPB * k] = m4[tid + TPB * k];
        if (tid < D / 4)
            reinterpret_cast<float4*>(smem + SM_WL)[tid] =
                reinterpret_cast<const float4*>(&g_wl[h][0])[tid];
    }

    // --- Convert A fragments in registers (mma layout: a0=row0/klo, a1=row1/klo,
    //     a2=row0/khi, a3=row1/khi)
    uint32_t af[4][4];
    #pragma unroll
    for (int kt = 0; kt < 4; kt++) {
        af[kt][0] = h2_of(o0lo[kt]);
        af[kt][1] = h2_of(o1lo[kt]);
        af[kt][2] = h2_of(o0hi[kt]);
        af[kt][3] = h2_of(o1hi[kt]);
    }
    __syncthreads();   // guards only the M/wl staging

    // --- GEMM strip: warp rows wid*16..+16, cols 0..64; acc[ct][4]
    float acc[8][4];
    #pragma unroll
    for (int ct = 0; ct < 8; ct++)
        #pragma unroll
        for (int e = 0; e < 4; e++) acc[ct][e] = 0.0f;

    const int lm = lid >> 3;
    const int lr = lid & 7;

    #pragma unroll
    for (int kt = 0; kt < 4; kt++) {
        uint32_t bb[8][2];
        #pragma unroll
        for (int cp = 0; cp < 4; cp++) {
            const int n  = cp * 16 + (lm >> 1) * 8 + lr;
            const int kb = kt * 32 + (lm & 1) * 16;
            ldm_x4(&bb[cp * 2][0], sbase + SM_M + n * 128 + (kb ^ ((n & 7) << 4)));
        }
        #pragma unroll
        for (int ct = 0; ct < 8; ct++)
            mma_f16(acc[ct], af[kt], bb[ct]);
    }

    // --- Epilogue: val[p] = b + sum_n o[p][n]*(wl[n] + T[p][n]), o in fp32.
    //     n0 = ct*8 + 2tig -> kt = ct>>1; even ct uses k-lo pair, odd k-hi.
    const float* wl = reinterpret_cast<const float*>(smem + SM_WL);

    float s0 = 0.0f, s1 = 0.0f;
    #pragma unroll
    for (int ct = 0; ct < 8; ct++) {
        const int n0 = ct * 8 + 2 * tig;
        const int kt = ct >> 1;
        const float2 of0 = (ct & 1) ? o0hi[kt] : o0lo[kt];
        const float2 of1 = (ct & 1) ? o1hi[kt] : o1lo[kt];
        const float2 wlv = *reinterpret_cast<const float2*>(&wl[n0]);
        s0 = fmaf(of0.x, wlv.x + acc[ct][0], s0);
        s0 = fmaf(of0.y, wlv.y + acc[ct][1], s0);
        s1 = fmaf(of1.x, wlv.x + acc[ct][2], s1);
        s1 = fmaf(of1.y, wlv.y + acc[ct][3], s1);
    }
    s0 += __shfl_xor_sync(0xffffffffu, s0, 1);
    s0 += __shfl_xor_sync(0xffffffffu, s0, 2);
    s1 += __shfl_xor_sync(0xffffffffu, s1, 1);
    s1 += __shfl_xor_sync(0xffffffffu, s1, 2);
    if (tig == 0) {
        out[(size_t)(pbase + wid * 16 + gid)     * HH + h] = s0 + bval;
        out[(size_t)(pbase + wid * 16 + gid + 8) * HH + h] = s1 + bval;
    }
}

// ---------------------------------------------------------------------------
extern "C" void kernel_launch(void* const* d_in, const int* in_sizes, int n_in,
                              void* d_out, int out_size) {
    const float* obs = (const float*)d_in[0];
    const float* w   = (const float*)d_in[1];
    const float* b   = (const float*)d_in[2];
    float* out       = (float*)d_out;

    const int N = in_sizes[0] / (HH * D);   // 1024

    prep_kernel<<<HH, 512>>>(w);

    cudaFuncSetAttribute(vf_kernel, cudaFuncAttributeMaxDynamicSharedMemorySize, SM_TOT);
    dim3 grid(N / 64, HH);                  // (16, 64) = 1024 blocks x 4 warps
    vf_kernel<<<grid, TPB, SM_TOT>>>(obs, b, out);
}

// round 14
// speedup vs baseline: 1.2149x; 1.2149x over previous
#include <cuda_runtime.h>
#include <cuda_fp16.h>
#include <cstdint>

#define D        64
#define HH       64
#define D_INPUT  2145
#define TPB      128

// Pre-swizzled (SW128) fp16 image of M = 1/2(Wu+Wu^T) (diag unhalved).
// Row = n (output dim), col = k (reduction dim). 64 x 128B per h.
__device__ __align__(16) uint8_t g_M[HH][D * 128];
__device__ float g_wl[HH][D];

#define SWZ(off) ((off) ^ (((off) >> 3) & 0x70))

__device__ __forceinline__ uint32_t smem_u32(const void* p) {
    uint32_t a;
    asm("{ .reg .u64 t; cvta.to.shared.u64 t, %1; cvt.u32.u64 %0, t; }" : "=r"(a) : "l"(p));
    return a;
}
__device__ __forceinline__ void ldm_x4(uint32_t* r, uint32_t addr) {
    asm volatile("ldmatrix.sync.aligned.m8n8.x4.shared.b16 {%0,%1,%2,%3}, [%4];"
        : "=r"(r[0]), "=r"(r[1]), "=r"(r[2]), "=r"(r[3]) : "r"(addr));
}
__device__ __forceinline__ void mma_f16(float* c, const uint32_t* a, const uint32_t* b) {
    asm volatile("mma.sync.aligned.m16n8k16.row.col.f32.f16.f16.f32 "
        "{%0,%1,%2,%3}, {%4,%5,%6,%7}, {%8,%9}, {%0,%1,%2,%3};"
        : "+f"(c[0]), "+f"(c[1]), "+f"(c[2]), "+f"(c[3])
        : "r"(a[0]), "r"(a[1]), "r"(a[2]), "r"(a[3]), "r"(b[0]), "r"(b[1]));
}

// ---------------------------------------------------------------------------
// Prep: stage w row into smem; 512 threads emit one 16B fp16 chunk of the
// symmetric M image. w[h][64+base(i)+(j-i)], base(i)=i*64-i(i-1)/2.
// ---------------------------------------------------------------------------
__global__ void prep_kernel(const float* __restrict__ w) {
    __shared__ float sw[D_INPUT];
    const int h = blockIdx.x;
    for (int i = threadIdx.x; i < D_INPUT; i += 512)
        sw[i] = w[(size_t)h * D_INPUT + i];
    __syncthreads();

    const int t  = threadIdx.x;
    const int n  = t >> 3;
    const int kq = t & 7;

    union { __half b[8]; float4 f; } hb;
    #pragma unroll
    for (int e = 0; e < 8; e++) {
        const int k = kq * 8 + e;
        const int i = k < n ? k : n;
        const int j = k < n ? n : k;
        const float v = sw[D + i * D - (i * (i - 1)) / 2 + (j - i)];
        hb.b[e] = __float2half_rn((k == n) ? v : 0.5f * v);
    }
    const uint32_t sw16 = SWZ((uint32_t)(n * 128 + kq * 16));
    *reinterpret_cast<float4*>(&g_M[h][sw16]) = hb.f;
    if (t < D) g_wl[h][t] = sw[t];
}

// ---------------------------------------------------------------------------
// Main: block = (64-path tile, h), 128 threads / 4 warps. Warp wid owns rows
// wid*16..+16, all 64 cols. Single fp16 pass: T = O*M. A fragments retained
// across kt for the epilogue (they hold exactly the o values matching the
// accumulator layout): val = b + sum_n o_n*(wl_n + T_n)
// ---------------------------------------------------------------------------
#define SM_O    0                       // 64 x 128B fp16 obs image (SW128)
#define SM_M    8192                    // 64 x 128B fp16 M image
#define SM_WL   16384                   // 64 fp32
#define SM_TOT  (SM_WL + 256)           // 16640 B

extern __shared__ char smem[];

__global__ __launch_bounds__(TPB, 6)
void vf_kernel(const float* __restrict__ obs,
               const float* __restrict__ biases,
               float* __restrict__ out) {
    const int h     = blockIdx.y;
    const int pbase = blockIdx.x * 64;
    const int tid   = threadIdx.x;
    const int wid   = tid >> 5;
    const int lid   = tid & 31;
    const uint32_t sbase = smem_u32(smem);

    // Hoist bias off the tail critical path
    const float bval = biases[h];

    // --- Front-batch obs LDGs: 64 rows x 16 float4, 8/thread (coalesced)
    float4 ov[8];
    #pragma unroll
    for (int k = 0; k < 8; k++) {
        const int f = tid + TPB * k;
        const int p = f >> 4;
        const int q = f & 15;
        ov[k] = reinterpret_cast<const float4*>(obs)
            [(size_t)(pbase + p) * (HH * D / 4) + (size_t)h * (D / 4) + q];
    }

    // --- Stage M image (pre-swizzled fp16): 512 float4, 4/thread; + wl
    {
        const float4* m4 = reinterpret_cast<const float4*>(&g_M[h][0]);
        float4* sm4 = reinterpret_cast<float4*>(smem + SM_M);
        #pragma unroll
        for (int k = 0; k < 4; k++) sm4[tid + TPB * k] = m4[tid + TPB * k];
        if (tid < D / 4)
            reinterpret_cast<float4*>(smem + SM_WL)[tid] =
                reinterpret_cast<const float4*>(&g_wl[h][0])[tid];
    }

    // --- Convert + store obs image
    #pragma unroll
    for (int k = 0; k < 8; k++) {
        const int f = tid + TPB * k;
        const int p = f >> 4;
        const int q = f & 15;
        const __half2 h01 = __floats2half2_rn(ov[k].x, ov[k].y);
        const __half2 h23 = __floats2half2_rn(ov[k].z, ov[k].w);
        const uint32_t sw = SWZ((uint32_t)(p * 128 + q * 8));
        *reinterpret_cast<uint2*>(smem + SM_O + sw) =
            make_uint2(*reinterpret_cast<const uint32_t*>(&h01),
                       *reinterpret_cast<const uint32_t*>(&h23));
    }
    __syncthreads();

    // --- GEMM strip: warp rows wid*16..+16, cols 0..64; acc[ct][4].
    //     A fragments af[kt][4] RETAINED for the epilogue.
    float acc[8][4];
    #pragma unroll
    for (int ct = 0; ct < 8; ct++)
        #pragma unroll
        for (int e = 0; e < 4; e++) acc[ct][e] = 0.0f;

    const int lm = lid >> 3;
    const int lr = lid & 7;

    uint32_t af[4][4];
    #pragma unroll
    for (int kt = 0; kt < 4; kt++) {
        {
            const int row = wid * 16 + (lm & 1) * 8 + lr;
            const int kb  = kt * 32 + (lm >> 1) * 16;
            ldm_x4(af[kt], sbase + SM_O + row * 128 + (kb ^ ((row & 7) << 4)));
        }
        uint32_t bb[8][2];
        #pragma unroll
        for (int cp = 0; cp < 4; cp++) {
            const int n  = cp * 16 + (lm >> 1) * 8 + lr;
            const int kb = kt * 32 + (lm & 1) * 16;
            ldm_x4(&bb[cp * 2][0], sbase + SM_M + n * 128 + (kb ^ ((n & 7) << 4)));
        }
        #pragma unroll
        for (int ct = 0; ct < 8; ct++)
            mma_f16(acc[ct], af[kt], bb[ct]);
    }

    // --- Epilogue: val[p] = b + sum_n o[p][n] * (wl[n] + T[p][n]).
    // o pairs from retained A fragments: n = ct*8 + 2*tig -> kt = ct>>1,
    // a-index = (ct&1)?{2,3}:{0,1}
    const int tig = lid & 3;
    const float* wl = reinterpret_cast<const float*>(smem + SM_WL);

    float s0 = 0.0f, s1 = 0.0f;
    #pragma unroll
    for (int ct = 0; ct < 8; ct++) {
        const int n0 = ct * 8 + 2 * tig;
        const int kt = ct >> 1;
        const int ai = (ct & 1) << 1;
        const float2 of0 = __half22float2(*reinterpret_cast<const __half2*>(&af[kt][ai]));
        const float2 of1 = __half22float2(*reinterpret_cast<const __half2*>(&af[kt][ai + 1]));
        const float2 wlv = *reinterpret_cast<const float2*>(&wl[n0]);
        s0 = fmaf(of0.x, wlv.x + acc[ct][0], s0);
        s0 = fmaf(of0.y, wlv.y + acc[ct][1], s0);
        s1 = fmaf(of1.x, wlv.x + acc[ct][2], s1);
        s1 = fmaf(of1.y, wlv.y + acc[ct][3], s1);
    }
    s0 += __shfl_xor_sync(0xffffffffu, s0, 1);
    s0 += __shfl_xor_sync(0xffffffffu, s0, 2);
    s1 += __shfl_xor_sync(0xffffffffu, s1, 1);
    s1 += __shfl_xor_sync(0xffffffffu, s1, 2);
    if (tig == 0) {
        const int gid = lid >> 2;
        out[(size_t)(pbase + wid * 16 + gid)     * HH + h] = s0 + bval;
        out[(size_t)(pbase + wid * 16 + gid + 8) * HH + h] = s1 + bval;
    }
}

// ---------------------------------------------------------------------------
extern "C" void kernel_launch(void* const* d_in, const int* in_sizes, int n_in,
                              void* d_out, int out_size) {
    const float* obs = (const float*)d_in[0];
    const float* w   = (const float*)d_in[1];
    const float* b   = (const float*)d_in[2];
    float* out       = (float*)d_out;

    const int N = in_sizes[0] / (HH * D);   // 1024

    prep_kernel<<<HH, 512>>>(w);

    cudaFuncSetAttribute(vf_kernel, cudaFuncAttributeMaxDynamicSharedMemorySize, SM_TOT);
    dim3 grid(N / 64, HH);                  // (16, 64) = 1024 blocks x 4 warps
    vf_kernel<<<grid, TPB, SM_TOT>>>(obs, b, out);
}